// round 17
// baseline (speedup 1.0000x reference)
#include <cuda_runtime.h>
#include <math.h>

// Problem constants (fixed by the reference).
#define BB 8
#define CC 16
#define NNDIM 512
#define EE 1024
#define POS_PER_B    (NNDIM * NNDIM)        // 262,144
#define GROUPS_PER_B (POS_PER_B / 4)        // 65,536 float4 groups per batch
#define SLOTS 55                            // blocks per batch
#define PBLK (BB * SLOTS)                   // 440 blocks (one wave)
#define BSTRIDE (SLOTS * 256)               // 14,080 groups
#define HASH_SZ 4096

// Globals — statically zero-initialized at module load; the ticket WINNER
// resets them after finalizing, so every graph replay sees zeros again.
// Hash lives in GLOBAL memory (zero smem -> full L1 carveout for streaming;
// R12's static __shared__ hash was charged to all 440 blocks and cut DRAM
// to 45%).
__device__ double g_sum[BB];
__device__ double g_cnt[BB];
__device__ unsigned int g_done;
__device__ int g_hkey[BB * HASH_SZ];
__device__ int g_hval[BB * HASH_SZ];

// ---------------------------------------------------------------------------
// Single fused kernel, grid = 440 (one wave; 148 SMs x 3).
//  Streaming (ALL blocks) — R16's measured-best body, byte-identical:
//    block -> batch b = blockIdx.x & 7, slot bb = blockIdx.x >> 3;
//    groups g = bb*256 + t + k*14080 (static induction). Hot loop = ONLY
//    loads + math: 16 class float4 loads staged in registers (MLP_p1=16,
//    __ldcs evict-first), log-sum-exp with label 0, masked accumulate into
//    per-thread registers. bb 0..35 run 5 iterations; bb 36..54 run 4.
//  Corr (bb==54 blocks only — one per batch, ~6us slack vs the critical
//    path): exact last-write-wins dedup of the batch's 1024 edges via a
//    GLOBAL O(E) hash (atomicCAS slot claim + atomicMax edge index),
//    accumulating (x_class0 - x_attr) at masked-valid cells directly into
//    the thread-local `sum` register — it rides the normal retirement path.
//  Retirement: one block reduction + double-atomic pair into g_sum/g_cnt;
//    last block (ticket) computes the batch-mean scalar, writes out, and
//    RESETS g_sum/g_cnt/g_done for the next graph replay.
// ---------------------------------------------------------------------------
__global__ void __launch_bounds__(256, 3) loss_kernel(
        const float* __restrict__ adj,
        const unsigned char* __restrict__ mask,
        const int* __restrict__ edge_index,
        const int* __restrict__ edge_attr,
        float* __restrict__ out) {
    const int t    = threadIdx.x;
    const int lane = t & 31, warp = t >> 5;
    const int b    = blockIdx.x & (BB - 1);
    const int bb   = blockIdx.x >> 3;        // 0..54 slot within batch
    __shared__ float r_sum[8];
    __shared__ float r_cnt[8];

    const float* adj_b = adj + (size_t)b * CC * POS_PER_B;
    const unsigned char* mask_b = mask + (size_t)b * POS_PER_B;

    float sum = 0.0f, cnt = 0.0f;

    // ---- edge-label correction (bb==54 blocks; global hash, no smem) ----
    if (bb == SLOTS - 1) {
        int* hkey = g_hkey + b * HASH_SZ;
        int* hval = g_hval + b * HASH_SZ;
        #pragma unroll
        for (int j = 0; j < HASH_SZ / 256; j++) {
            hkey[t + j * 256] = -1;
            hval[t + j * 256] = -1;
        }
        __syncthreads();

        const int2* ei = reinterpret_cast<const int2*>(edge_index)
                       + (size_t)b * EE;
        int key[4], attr[4];
        unsigned hh[4];
        #pragma unroll
        for (int j = 0; j < 4; j++) {
            const int e = t + j * 256;
            const int2 rc = ei[e];
            key[j]  = (rc.x << 9) | rc.y;
            attr[j] = edge_attr[b * EE + e];
            unsigned h = (((unsigned)key[j] * 2654435761u) >> 20) & (HASH_SZ - 1);
            while (true) {
                int old = atomicCAS(&hkey[h], -1, key[j]);
                if (old == -1 || old == key[j]) { atomicMax(&hval[h], e); break; }
                h = (h + 1) & (HASH_SZ - 1);
            }
            hh[j] = h;
        }
        __syncthreads();

        #pragma unroll
        for (int j = 0; j < 4; j++) {
            const int e = t + j * 256;
            if (hval[hh[j]] == e && attr[j] != 0) {      // live, nonzero attr
                const int cell = (key[j] >> 9) * NNDIM + (key[j] & (NNDIM - 1));
                if (mask_b[cell]) {
                    const float* p = adj_b + cell;
                    sum += p[0] - p[(size_t)attr[j] * POS_PER_B]; // x0 -> xa
                }
            }
        }
    }

    // ---- streaming: static schedule, lean hot loop (R16-exact) ----
    for (int g = bb * 256 + t; g < GROUPS_PER_B; g += BSTRIDE) {
        const float4* base = reinterpret_cast<const float4*>(adj_b + (g << 2));
        const uchar4 m4 = *reinterpret_cast<const uchar4*>(mask_b + (g << 2));

        // phase 1: batched loads (16 independent LDG.128)
        float4 v[CC];
        #pragma unroll
        for (int c = 0; c < CC; c++)
            v[c] = __ldcs(base + (size_t)c * (POS_PER_B / 4));

        // phase 2: exp / accumulate
        float s0 = __expf(v[0].x), s1 = __expf(v[0].y);
        float s2 = __expf(v[0].z), s3 = __expf(v[0].w);
        #pragma unroll
        for (int c = 1; c < CC; c++) {
            s0 += __expf(v[c].x); s1 += __expf(v[c].y);
            s2 += __expf(v[c].z); s3 += __expf(v[c].w);
        }
        if (m4.x) { sum += __logf(s0) - v[0].x; cnt += 1.0f; }
        if (m4.y) { sum += __logf(s1) - v[0].y; cnt += 1.0f; }
        if (m4.z) { sum += __logf(s2) - v[0].z; cnt += 1.0f; }
        if (m4.w) { sum += __logf(s3) - v[0].w; cnt += 1.0f; }
    }

    // ---- single retirement reduction (all 8 warps share batch b) ----
    #pragma unroll
    for (int off = 16; off > 0; off >>= 1) {
        sum += __shfl_down_sync(0xFFFFFFFFu, sum, off);
        cnt += __shfl_down_sync(0xFFFFFFFFu, cnt, off);
    }
    if (lane == 0) { r_sum[warp] = sum; r_cnt[warp] = cnt; }
    __syncthreads();

    if (t == 0) {
        float bs = 0.0f, bc = 0.0f;
        #pragma unroll
        for (int w = 0; w < 8; w++) { bs += r_sum[w]; bc += r_cnt[w]; }
        atomicAdd(&g_sum[b], (double)bs);
        atomicAdd(&g_cnt[b], (double)bc);

        __threadfence();
        const unsigned ticket = atomicAdd(&g_done, 1u);
        if (ticket == PBLK - 1) {
            double acc = 0.0;
            #pragma unroll
            for (int i = 0; i < BB; i++) {
                volatile double* vs = g_sum;
                volatile double* vc = g_cnt;
                double c = vc[i];
                if (c < 1.0) c = 1.0;
                acc += vs[i] / c;
            }
            out[0] = (float)(acc / (double)BB);
            // Reset globals so the next graph replay sees zeros again.
            #pragma unroll
            for (int i = 0; i < BB; i++) { g_sum[i] = 0.0; g_cnt[i] = 0.0; }
            g_done = 0u;
        }
    }
}

// ---------------------------------------------------------------------------
// kernel_launch — inputs (metadata order): adj f32 [B,C,N,N], mask bool(u8)
// [B,N,N], edge_index i32 [B,E,2], edge_attr i32 [B,E]. Output: 1 fp32 scalar.
// ---------------------------------------------------------------------------
extern "C" void kernel_launch(void* const* d_in, const int* in_sizes, int n_in,
                              void* d_out, int out_size) {
    const float*         adj        = (const float*)d_in[0];
    const unsigned char* mask       = (const unsigned char*)d_in[1];
    const int*           edge_index = (const int*)d_in[2];
    const int*           edge_attr  = (const int*)d_in[3];
    float*               out        = (float*)d_out;

    loss_kernel<<<PBLK, 256>>>(adj, mask, edge_index, edge_attr, out);
}